// round 2
// baseline (speedup 1.0000x reference)
#include <cuda_runtime.h>
#include <math.h>
#include <stdint.h>

// Problem dims (fixed by the dataset)
#define Kk   256
#define Tt   512
#define NBb  256
#define Vv   4096

// A-cache config
#define RSM    216              // rows of A kept in shared memory
#define SPILL  (Kk - RSM)       // 40 rows streamed from L2 (chunk-major layout)
#define RP     260              // padded smem row stride (floats) -> conflict-free float4 LDS
#define NCHUNK (Kk / 4)         // 64 float4 chunks per row

#define NTHREADS 256
#define NCTAS    (NBb / 2)      // 128, 2 sequences per CTA

// ---------------- device scratch (static allocations only) ----------------
__device__ float g_expA [Kk * Kk];            // expA[i][j]   (bwd rows)
__device__ float g_expAT[Kk * Kk];            // expA^T[j][i] (fwd rows)
__device__ float g_spillF[NCHUNK * SPILL * 4];// fwd spill rows, chunk-major
__device__ float g_spillB[NCHUNK * SPILL * 4];// bwd spill rows, chunk-major
__device__ float g_logBt[Vv * Kk];            // log_B transposed: [v][j]

// ---------------- prep kernels ----------------
__global__ void prep_A(const float* __restrict__ logA) {
    int idx = blockIdx.x * blockDim.x + threadIdx.x;
    if (idx >= Kk * Kk) return;
    int i = idx / Kk, j = idx % Kk;
    float e = expf(logA[idx]);
    g_expA[idx] = e;
    g_expAT[j * Kk + i] = e;
    // fwd spill: row j of expA^T, element i  -> [chunk=i/4][r=j-RSM][c=i%4]
    if (j >= RSM) g_spillF[(i >> 2) * (SPILL * 4) + (j - RSM) * 4 + (i & 3)] = e;
    // bwd spill: row i of expA, element j   -> [chunk=j/4][r=i-RSM][c=j%4]
    if (i >= RSM) g_spillB[(j >> 2) * (SPILL * 4) + (i - RSM) * 4 + (j & 3)] = e;
}

__global__ void prep_B(const float* __restrict__ logB) {
    int idx = blockIdx.x * blockDim.x + threadIdx.x;
    if (idx >= Vv * Kk) return;
    int v = idx / Kk, j = idx % Kk;
    g_logBt[idx] = logB[j * Vv + v];   // coalesced writes
}

// ---------------- block reductions (2 lanes of state per thread) ----------------
template <bool IS_MAX>
__device__ __forceinline__ void bred2(float& v0, float& v1, float* red) {
    #pragma unroll
    for (int o = 16; o; o >>= 1) {
        float u0 = __shfl_xor_sync(0xFFFFFFFFu, v0, o);
        float u1 = __shfl_xor_sync(0xFFFFFFFFu, v1, o);
        if (IS_MAX) { v0 = fmaxf(v0, u0); v1 = fmaxf(v1, u1); }
        else        { v0 += u0;           v1 += u1;           }
    }
    int wid = threadIdx.x >> 5;
    if ((threadIdx.x & 31) == 0) { red[wid] = v0; red[8 + wid] = v1; }
    __syncthreads();
    float r0 = red[0], r1 = red[8];
    #pragma unroll
    for (int w = 1; w < 8; w++) {
        if (IS_MAX) { r0 = fmaxf(r0, red[w]); r1 = fmaxf(r1, red[8 + w]); }
        else        { r0 += red[w];           r1 += red[8 + w];           }
    }
    v0 = r0; v1 = r1;
    __syncthreads();   // red reusable afterwards
}

__device__ __forceinline__ void normalize2(float& lg0, float& lg1, float* red) {
    float m0 = lg0, m1 = lg1;
    bred2<true>(m0, m1, red);
    float p0 = __expf(lg0 - m0), p1 = __expf(lg1 - m1);
    bred2<false>(p0, p1, red);
    lg0 -= m0 + logf(p0);
    lg1 -= m1 + logf(p1);
}

// ---------------- the dot: my-row (smem or L2 spill) . broadcast e-vectors ----------------
__device__ __forceinline__ void dot2(const float* __restrict__ As,
                                     const float* __restrict__ spill,
                                     const float* __restrict__ es,
                                     int tid, float& s0, float& s1) {
    const float4* e0 = reinterpret_cast<const float4*>(es);
    const float4* e1 = reinterpret_cast<const float4*>(es + Kk);
    float a00 = 0.f, a01 = 0.f, a10 = 0.f, a11 = 0.f;
    if (tid < RSM) {
        const float4* a = reinterpret_cast<const float4*>(As + tid * RP);
        #pragma unroll 16
        for (int q = 0; q < NCHUNK; q++) {
            float4 av = a[q]; float4 v0 = e0[q]; float4 v1 = e1[q];
            a00 = fmaf(av.x, v0.x, a00); a01 = fmaf(av.y, v0.y, a01);
            a00 = fmaf(av.z, v0.z, a00); a01 = fmaf(av.w, v0.w, a01);
            a10 = fmaf(av.x, v1.x, a10); a11 = fmaf(av.y, v1.y, a11);
            a10 = fmaf(av.z, v1.z, a10); a11 = fmaf(av.w, v1.w, a11);
        }
    } else {
        const float4* a = reinterpret_cast<const float4*>(spill) + (tid - RSM);
        #pragma unroll 8
        for (int q = 0; q < NCHUNK; q++) {
            float4 av = a[q * SPILL]; float4 v0 = e0[q]; float4 v1 = e1[q];
            a00 = fmaf(av.x, v0.x, a00); a01 = fmaf(av.y, v0.y, a01);
            a00 = fmaf(av.z, v0.z, a00); a01 = fmaf(av.w, v0.w, a01);
            a10 = fmaf(av.x, v1.x, a10); a11 = fmaf(av.y, v1.y, a11);
            a10 = fmaf(av.z, v1.z, a10); a11 = fmaf(av.w, v1.w, a11);
        }
    }
    s0 = a00 + a01;
    s1 = a10 + a11;
}

// ---------------- main persistent kernel: fwd + bwd + gamma ----------------
__global__ void __launch_bounds__(NTHREADS, 1)
hmm_fb(const float* __restrict__ logpi,
       const int*   __restrict__ obs,
       float*       __restrict__ out) {
    extern __shared__ float sm[];
    float* As    = sm;                      // RSM*RP floats
    float* es    = As + RSM * RP;           // 2*Kk
    float* red   = es + 2 * Kk;             // 16
    int*   obs_s = (int*)(red + 16);        // 2*Tt ints

    const int tid = threadIdx.x;
    const int c   = blockIdx.x;
    const int n0  = 2 * c, n1 = 2 * c + 1;
    const int wid = tid >> 5, lane = tid & 31;

    // preload this CTA's two observation sequences
    for (int i = tid; i < Tt; i += NTHREADS) {
        obs_s[i]      = obs[n0 * Tt + i];
        obs_s[Tt + i] = obs[n1 * Tt + i];
    }

    // fill A-cache with expA^T rows (forward phase)
    for (int r = wid; r < RSM; r += 8) {
        const float4* src = reinterpret_cast<const float4*>(g_expAT + r * Kk);
        float4*       dst = reinterpret_cast<float4*>(As + r * RP);
        for (int q = lane; q < NCHUNK; q += 32) dst[q] = src[q];
    }
    __syncthreads();

    // ---- forward ----
    float lp = logpi[tid];
    float a0 = lp + g_logBt[obs_s[0]  * Kk + tid];
    float a1 = lp + g_logBt[obs_s[Tt] * Kk + tid];
    float* out0 = out + (size_t)n0 * Tt * Kk + tid;
    float* out1 = out + (size_t)n1 * Tt * Kk + tid;
    out0[0] = a0; out1[0] = a1;

    for (int t = 1; t < Tt; ++t) {
        float m0 = a0, m1 = a1;
        bred2<true>(m0, m1, red);
        es[tid]      = __expf(a0 - m0);
        es[Kk + tid] = __expf(a1 - m1);
        __syncthreads();
        float s0, s1;
        dot2(As, g_spillF, es, tid, s0, s1);
        int o0 = obs_s[t], o1 = obs_s[Tt + t];
        a0 = g_logBt[o0 * Kk + tid] + m0 + logf(s0);
        a1 = g_logBt[o1 * Kk + tid] + m1 + logf(s1);
        out0[(size_t)t * Kk] = a0;
        out1[(size_t)t * Kk] = a1;
        // no trailing sync needed: next bred2's internal barriers order es/red reuse
    }
    __syncthreads();

    // refill A-cache with expA rows (backward phase)
    for (int r = wid; r < RSM; r += 8) {
        const float4* src = reinterpret_cast<const float4*>(g_expA + r * Kk);
        float4*       dst = reinterpret_cast<float4*>(As + r * RP);
        for (int q = lane; q < NCHUNK; q += 32) dst[q] = src[q];
    }
    __syncthreads();

    // ---- backward + gamma (in place over alpha stored in out) ----
    float b0r = 0.f, b1r = 0.f;   // log beta, carried per thread
    {
        float lg0 = out0[(size_t)(Tt - 1) * Kk];
        float lg1 = out1[(size_t)(Tt - 1) * Kk];
        normalize2(lg0, lg1, red);
        out0[(size_t)(Tt - 1) * Kk] = lg0;
        out1[(size_t)(Tt - 1) * Kk] = lg1;
    }
    for (int t = Tt - 2; t >= 0; --t) {
        int o0 = obs_s[t + 1], o1 = obs_s[Tt + t + 1];
        float x0 = g_logBt[o0 * Kk + tid] + b0r;
        float x1 = g_logBt[o1 * Kk + tid] + b1r;
        float m0 = x0, m1 = x1;
        bred2<true>(m0, m1, red);
        es[tid]      = __expf(x0 - m0);
        es[Kk + tid] = __expf(x1 - m1);
        __syncthreads();
        float s0, s1;
        dot2(As, g_spillB, es, tid, s0, s1);
        b0r = m0 + logf(s0);
        b1r = m1 + logf(s1);
        float lg0 = out0[(size_t)t * Kk] + b0r;
        float lg1 = out1[(size_t)t * Kk] + b1r;
        normalize2(lg0, lg1, red);
        out0[(size_t)t * Kk] = lg0;
        out1[(size_t)t * Kk] = lg1;
    }
}

// ---------------- launch ----------------
extern "C" void kernel_launch(void* const* d_in, const int* in_sizes, int n_in,
                              void* d_out, int out_size) {
    const float* log_pi = (const float*)d_in[0];
    const float* log_A  = (const float*)d_in[1];
    const float* log_B  = (const float*)d_in[2];
    const int*   observ = (const int*)  d_in[3];
    float* out = (float*)d_out;

    // dynamic smem: A-cache + e-vectors + reduction scratch + obs
    const int smem_bytes = (RSM * RP + 2 * Kk + 16) * 4 + 2 * Tt * 4;
    cudaFuncSetAttribute(hmm_fb, cudaFuncAttributeMaxDynamicSharedMemorySize, smem_bytes);

    prep_A<<<(Kk * Kk + 255) / 256, 256>>>(log_A);
    prep_B<<<(Vv * Kk + 255) / 256, 256>>>(log_B);
    hmm_fb<<<NCTAS, NTHREADS, smem_bytes>>>(log_pi, observ, out);
}

// round 3
// speedup vs baseline: 1.9540x; 1.9540x over previous
#include <cuda_runtime.h>
#include <math.h>
#include <stdint.h>

#define Kk 256
#define Tt 512
#define NBb 256
#define Vv 4096

#define NT 256
#define NC (NBb/2)          // 128 CTAs, 2 sequences each
#define REGF 128            // floats of my A-row held in registers
#define REGU (REGF/2)       // 64 u64 packed pairs
#define SMF  (Kk - REGF)    // 128 floats per row in smem
#define RP2  132            // padded smem row stride in floats (528B: 16B-mult, conflict-free)
#define RQ   (REGF/4)       // 32 reg chunks (float4-granularity)
#define SQ   (SMF/4)        // 32 smem chunks

typedef unsigned long long ull;

// ---------------- device scratch ----------------
__device__ __align__(16) float g_AT[Kk*Kk];   // expA^T rows (forward)
__device__ __align__(16) float g_A [Kk*Kk];   // expA rows   (backward)
__device__ __align__(16) float g_Bt[Vv*Kk];   // exp(log_B) transposed: [v][j]
__device__ __align__(16) float g_pi[Kk];      // exp(log_pi)

// ---------------- prep ----------------
__global__ void prep_A(const float* __restrict__ logA, const float* __restrict__ logpi) {
    int idx = blockIdx.x * blockDim.x + threadIdx.x;
    if (idx < Kk*Kk) {
        int i = idx / Kk, j = idx % Kk;
        float e = expf(logA[idx]);
        g_A[idx] = e;
        g_AT[j*Kk + i] = e;
    }
    if (idx < Kk) g_pi[idx] = expf(logpi[idx]);
}

__global__ void prep_B(const float* __restrict__ logB) {
    int idx = blockIdx.x * blockDim.x + threadIdx.x;   // over j*Vv + v (coalesced read)
    if (idx >= Kk*Vv) return;
    int j = idx / Vv, v = idx % Vv;
    g_Bt[v*Kk + j] = expf(logB[idx]);
}

// ---------------- f32x2 helpers ----------------
__device__ __forceinline__ void ffma2(ull& d, ull a, ull b) {
    asm("fma.rn.f32x2 %0, %1, %2, %0;" : "+l"(d) : "l"(a), "l"(b));
}
__device__ __forceinline__ float pair_sum(ull a, ull b) {
    ull s; asm("add.rn.f32x2 %0, %1, %2;" : "=l"(s) : "l"(a), "l"(b));
    unsigned lo, hi; asm("mov.b64 {%0,%1}, %2;" : "=r"(lo), "=r"(hi) : "l"(s));
    return __uint_as_float(lo) + __uint_as_float(hi);
}

__device__ __forceinline__ void wred2(float& v0, float& v1) {
    #pragma unroll
    for (int o = 16; o; o >>= 1) {
        v0 += __shfl_xor_sync(0xFFFFFFFFu, v0, o);
        v1 += __shfl_xor_sync(0xFFFFFFFFu, v1, o);
    }
}

// dot of my A-row (regs + smem) against two broadcast e-vectors
__device__ __forceinline__ void dot2(const ull (&ra)[REGU],
                                     const float* __restrict__ Asrow,
                                     const float* __restrict__ es0,
                                     const float* __restrict__ es1,
                                     float& s0, float& s1) {
    ull a00 = 0, a01 = 0, a10 = 0, a11 = 0;
    const ulonglong2* e0 = reinterpret_cast<const ulonglong2*>(es0);
    const ulonglong2* e1 = reinterpret_cast<const ulonglong2*>(es1);
    #pragma unroll
    for (int q = 0; q < RQ; q++) {
        ulonglong2 v0 = e0[q], v1 = e1[q];
        ffma2(a00, ra[2*q],   v0.x); ffma2(a01, ra[2*q+1], v0.y);
        ffma2(a10, ra[2*q],   v1.x); ffma2(a11, ra[2*q+1], v1.y);
    }
    const ulonglong2* Ar = reinterpret_cast<const ulonglong2*>(Asrow);
    #pragma unroll
    for (int q = 0; q < SQ; q++) {
        ulonglong2 av = Ar[q];
        ulonglong2 v0 = e0[RQ+q], v1 = e1[RQ+q];
        ffma2(a00, av.x, v0.x); ffma2(a01, av.y, v0.y);
        ffma2(a10, av.x, v1.x); ffma2(a11, av.y, v1.y);
    }
    s0 = pair_sum(a00, a01);
    s1 = pair_sum(a10, a11);
}

// ---------------- main persistent kernel ----------------
__global__ void __launch_bounds__(NT, 1)
hmm_fb(const int* __restrict__ obs, float* __restrict__ out) {
    extern __shared__ float sm[];
    float* As    = sm;                 // Kk * RP2
    float* esb   = As + Kk*RP2;        // [2 buf][2 seq][Kk]
    float* red   = esb + 2*2*Kk;       // [2 buf][16]
    int*   obs_s = (int*)(red + 32);   // [2 seq][Tt]

    const int tid = threadIdx.x, wid = tid >> 5, lane = tid & 31;
    const int n0 = 2*blockIdx.x, n1 = n0 + 1;

    for (int i = tid; i < Tt; i += NT) {
        obs_s[i]      = obs[n0*Tt + i];
        obs_s[Tt + i] = obs[n1*Tt + i];
    }

    ull ra[REGU];
    // --- load forward A-cache (expA^T): regs cols [0,128), smem cols [128,256) ---
    {
        const ull* src = reinterpret_cast<const ull*>(g_AT + tid*Kk);
        #pragma unroll
        for (int k = 0; k < REGU; k++) ra[k] = src[k];
        for (int r = wid; r < Kk; r += 8) {
            const float4* s4 = reinterpret_cast<const float4*>(g_AT + r*Kk + REGF);
            float4*       d4 = reinterpret_cast<float4*>(As + r*RP2);
            if (lane < SQ) d4[lane] = s4[lane];
        }
    }
    __syncthreads();

    float* out0 = out + (size_t)n0*Tt*Kk + tid;
    float* out1 = out + (size_t)n1*Tt*Kk + tid;
    const float* Asrow = As + tid*RP2;

    int b = 0;
    float w0, w1;

    // ---- forward init (t = 0): u0 = pi * B[:,o0] ----
    {
        float pi = g_pi[tid];
        w0 = pi * g_Bt[obs_s[0]  * Kk + tid];
        w1 = pi * g_Bt[obs_s[Tt] * Kk + tid];
        esb[tid]      = w0;
        esb[Kk + tid] = w1;
        float r0 = w0, r1 = w1; wred2(r0, r1);
        if (!lane) { red[wid] = r0; red[8 + wid] = r1; }
        __syncthreads();
    }

    // ---- forward loop ----
    for (int t = 1; t < Tt; t++) {
        float c0 = 0.f, c1 = 0.f;
        #pragma unroll
        for (int k = 0; k < 8; k++) { c0 += red[b*16 + k]; c1 += red[b*16 + 8 + k]; }
        float r0 = __fdividef(1.f, c0), r1 = __fdividef(1.f, c1);
        // store normalized p_{t-1}
        out0[(size_t)(t-1)*Kk] = w0 * r0;
        out1[(size_t)(t-1)*Kk] = w1 * r1;
        // prefetch emissions for time t
        float bb0 = g_Bt[obs_s[t]      * Kk + tid];
        float bb1 = g_Bt[obs_s[Tt + t] * Kk + tid];
        // q_j = sum_i u_i * A[i][j]  (unnormalized; scale by r after)
        float s0, s1;
        dot2(ra, Asrow, esb + b*2*Kk, esb + b*2*Kk + Kk, s0, s1);
        int nb = b ^ 1;
        w0 = s0 * r0 * bb0;
        w1 = s1 * r1 * bb1;
        esb[nb*2*Kk + tid]      = w0;
        esb[nb*2*Kk + Kk + tid] = w1;
        float p0 = w0, p1 = w1; wred2(p0, p1);
        if (!lane) { red[nb*16 + wid] = p0; red[nb*16 + 8 + wid] = p1; }
        __syncthreads();
        b = nb;
    }
    // store p_{T-1}
    {
        float c0 = 0.f, c1 = 0.f;
        #pragma unroll
        for (int k = 0; k < 8; k++) { c0 += red[b*16 + k]; c1 += red[b*16 + 8 + k]; }
        out0[(size_t)(Tt-1)*Kk] = w0 * __fdividef(1.f, c0);
        out1[(size_t)(Tt-1)*Kk] = w1 * __fdividef(1.f, c1);
    }
    __syncthreads();

    // --- refill A-cache for backward (expA rows) ---
    {
        const ull* src = reinterpret_cast<const ull*>(g_A + tid*Kk);
        #pragma unroll
        for (int k = 0; k < REGU; k++) ra[k] = src[k];
        for (int r = wid; r < Kk; r += 8) {
            const float4* s4 = reinterpret_cast<const float4*>(g_A + r*Kk + REGF);
            float4*       d4 = reinterpret_cast<float4*>(As + r*RP2);
            if (lane < SQ) d4[lane] = s4[lane];
        }
    }

    // ---- backward init: y_{T-1} = B[:,o_{T-1}] (beta = 1) ----
    b = 0;
    {
        float y0 = g_Bt[obs_s[Tt-1]      * Kk + tid];
        float y1 = g_Bt[obs_s[Tt + Tt-1] * Kk + tid];
        esb[tid]      = y0;
        esb[Kk + tid] = y1;
        float r0 = y0, r1 = y1; wred2(r0, r1);
        if (!lane) { red[wid] = r0; red[8 + wid] = r1; }
        __syncthreads();
    }

    // ---- backward loop: beta_t = A (B_{t+1} . beta_{t+1}); gamma_t = p_t . beta_t ----
    for (int t = Tt - 2; t >= 0; t--) {
        float c0 = 0.f, c1 = 0.f;
        #pragma unroll
        for (int k = 0; k < 8; k++) { c0 += red[b*16 + k]; c1 += red[b*16 + 8 + k]; }
        float r0 = __fdividef(1.f, c0), r1 = __fdividef(1.f, c1);
        // prefetch p_t and emission B[:,o_t]
        float p0  = out0[(size_t)t*Kk];
        float p1  = out1[(size_t)t*Kk];
        float bb0 = g_Bt[obs_s[t]      * Kk + tid];
        float bb1 = g_Bt[obs_s[Tt + t] * Kk + tid];
        float s0, s1;
        dot2(ra, Asrow, esb + b*2*Kk, esb + b*2*Kk + Kk, s0, s1);
        float be0 = s0 * r0, be1 = s1 * r1;       // scaled beta_t
        out0[(size_t)t*Kk] = p0 * be0;            // unnormalized gamma
        out1[(size_t)t*Kk] = p1 * be1;
        int nb = b ^ 1;
        float y0 = be0 * bb0, y1 = be1 * bb1;     // y_t = B_t . beta_t
        esb[nb*2*Kk + tid]      = y0;
        esb[nb*2*Kk + Kk + tid] = y1;
        float q0 = y0, q1 = y1; wred2(q0, q1);
        if (!lane) { red[nb*16 + wid] = q0; red[nb*16 + 8 + wid] = q1; }
        __syncthreads();
        b = nb;
    }
}

// ---------------- epilogue: per-(n,t) log-normalize ----------------
__global__ void __launch_bounds__(256)
norm_gamma(float* __restrict__ out) {
    int row  = (blockIdx.x << 3) + (threadIdx.x >> 5);   // one warp per (n,t) row
    int lane = threadIdx.x & 31;
    float4* p = reinterpret_cast<float4*>(out + (size_t)row * Kk);
    float4 v0 = p[lane], v1 = p[lane + 32];
    float s = v0.x + v0.y + v0.z + v0.w + v1.x + v1.y + v1.z + v1.w;
    #pragma unroll
    for (int o = 16; o; o >>= 1) s += __shfl_xor_sync(0xFFFFFFFFu, s, o);
    float lc = __logf(s);
    v0.x = __logf(v0.x) - lc; v0.y = __logf(v0.y) - lc;
    v0.z = __logf(v0.z) - lc; v0.w = __logf(v0.w) - lc;
    v1.x = __logf(v1.x) - lc; v1.y = __logf(v1.y) - lc;
    v1.z = __logf(v1.z) - lc; v1.w = __logf(v1.w) - lc;
    p[lane] = v0; p[lane + 32] = v1;
}

// ---------------- launch ----------------
extern "C" void kernel_launch(void* const* d_in, const int* in_sizes, int n_in,
                              void* d_out, int out_size) {
    const float* log_pi = (const float*)d_in[0];
    const float* log_A  = (const float*)d_in[1];
    const float* log_B  = (const float*)d_in[2];
    const int*   observ = (const int*)  d_in[3];
    float* out = (float*)d_out;

    const int smem_bytes = (Kk*RP2 + 2*2*Kk + 32) * 4 + 2*Tt*4;
    cudaFuncSetAttribute(hmm_fb, cudaFuncAttributeMaxDynamicSharedMemorySize, smem_bytes);

    prep_A<<<(Kk*Kk + 255)/256, 256>>>(log_A, log_pi);
    prep_B<<<(Kk*Vv + 255)/256, 256>>>(log_B);
    hmm_fb<<<NC, NT, smem_bytes>>>(observ, out);
    norm_gamma<<<(NBb*Tt)/8, 256>>>(out);
}